// round 1
// baseline (speedup 1.0000x reference)
#include <cuda_runtime.h>
#include <cuda_bf16.h>

// Problem constants (fixed by the dataset): B=4, I=64, O=64, K=3, H=W=512.
#define EPS_F 1e-8f

// Scratch for modulated+demodulated weights, layout [b][i][o][k] (k = ky*3+kx)
// so the conv kernel can stream 576 contiguous floats per (b, i).
// 4*64*64*9 floats = 2.36 MB -> stays L2-resident across the conv kernel.
__device__ float g_wmod[4 * 64 * 64 * 9];

// ---------------------------------------------------------------------------
// Kernel 1: per-(b,o) style modulation + demodulation.
// w[b,o,i,k] = weight[o,i,k] * style[b,i];  sigma = sqrt(EPS + sum w^2)
// g_wmod[b,i,o,k] = w / sigma
// One block per (b,o): 256 blocks x 256 threads. Negligible cost (~5 us).
// ---------------------------------------------------------------------------
__global__ void modulate_kernel(const float* __restrict__ weight,   // (O, I, 3, 3)
                                const float* __restrict__ style) {  // (B, I)
    const int bo  = blockIdx.x;
    const int b   = bo >> 6;
    const int o   = bo & 63;
    const int tid = threadIdx.x;

    __shared__ float red[8];
    __shared__ float s_inv;

    float sum = 0.f;
    for (int idx = tid; idx < 576; idx += 256) {
        const int i = idx / 9;
        const float v = weight[o * 576 + idx] * style[b * 64 + i];
        sum += v * v;
    }
    #pragma unroll
    for (int off = 16; off; off >>= 1)
        sum += __shfl_down_sync(0xffffffffu, sum, off);
    if ((tid & 31) == 0) red[tid >> 5] = sum;
    __syncthreads();
    if (tid == 0) {
        float t = 0.f;
        #pragma unroll
        for (int k = 0; k < 8; k++) t += red[k];
        s_inv = rsqrtf(EPS_F + t);
    }
    __syncthreads();
    const float inv = s_inv;

    for (int idx = tid; idx < 576; idx += 256) {
        const int i = idx / 9;
        const int k = idx - i * 9;
        const float v = weight[o * 576 + idx] * style[b * 64 + i] * inv;
        g_wmod[((b * 64 + i) * 64 + o) * 9 + k] = v;
    }
}

// ---------------------------------------------------------------------------
// Kernel 2: direct 3x3 conv, one block per (b, 16x16 output tile), all 64
// output channels computed in-block (input tile read once per block).
//
// Thread layout (256 threads = 8 warps):
//   warp  (tid>>5)   -> o-group: output channels [wid*8, wid*8+8)
//                       => weight smem reads are warp-uniform broadcasts
//   lane  (tid&31)   -> pgy = lane>>1 (pixel row 0..15),
//                       cbase = (lane&1)*8 (pixel cols cbase..cbase+7)
//
// Per input channel i: 576 FFMA vs ~102 LDS per thread -> FMA-pipe bound.
// ---------------------------------------------------------------------------
__global__ __launch_bounds__(256, 2)
void conv_kernel(const float* __restrict__ input,   // (B, I, 512, 512)
                 float* __restrict__ out) {         // (B, O, 512, 512)
    __shared__ float s_in[18 * 18];   // input tile + 1-px halo (stride 18: <=2-way conflicts)
    __shared__ float s_w[64 * 9];     // all 64 output-channel filters for channel i

    const int tid   = threadIdx.x;
    const int b     = blockIdx.z;
    const int h0    = blockIdx.y << 4;
    const int w0    = blockIdx.x << 4;
    const int wid   = tid >> 5;          // o-group
    const int lane  = tid & 31;
    const int pgy   = lane >> 1;         // pixel row in tile
    const int cbase = (lane & 1) << 3;   // pixel col base in tile

    float acc[8][8];
    #pragma unroll
    for (int o = 0; o < 8; o++)
        #pragma unroll
        for (int x = 0; x < 8; x++) acc[o][x] = 0.f;

    const float* in_b = input + (size_t)b * 64 * 512 * 512;
    const float* wm_b = g_wmod + (size_t)b * 64 * 64 * 9;

    for (int i = 0; i < 64; i++) {
        __syncthreads();  // protect smem from previous iteration's readers

        // --- load 18x18 input tile (zero-padded at image border) ---
        const float* in_c = in_b + (size_t)i * 512 * 512;
        for (int idx = tid; idx < 324; idx += 256) {
            const int r  = idx / 18;
            const int c  = idx - r * 18;
            const int gh = h0 + r - 1;
            const int gw = w0 + c - 1;
            float v = 0.f;
            if ((unsigned)gh < 512u && (unsigned)gw < 512u)
                v = in_c[gh * 512 + gw];
            s_in[idx] = v;
        }
        // --- load 64x9 modulated weights for channel i ---
        const float* wsrc = wm_b + (size_t)i * 64 * 9;
        for (int idx = tid; idx < 576; idx += 256)
            s_w[idx] = wsrc[idx];

        __syncthreads();

        // --- hoist 3x10 input neighborhood to registers ---
        float v[3][10];
        #pragma unroll
        for (int dy = 0; dy < 3; dy++)
            #pragma unroll
            for (int c = 0; c < 10; c++)
                v[dy][c] = s_in[(pgy + dy) * 18 + cbase + c];

        // --- 8 o-channels x 8 pixels x 9 taps = 576 FFMA ---
        #pragma unroll
        for (int o = 0; o < 8; o++) {
            float wr[9];
            const float* wp = s_w + ((wid << 3) + o) * 9;   // warp-uniform -> LDS broadcast
            #pragma unroll
            for (int k = 0; k < 9; k++) wr[k] = wp[k];
            #pragma unroll
            for (int x = 0; x < 8; x++) {
                float a = acc[o][x];
                #pragma unroll
                for (int dy = 0; dy < 3; dy++)
                    #pragma unroll
                    for (int dx = 0; dx < 3; dx++)
                        a += wr[dy * 3 + dx] * v[dy][x + dx];
                acc[o][x] = a;
            }
        }
    }

    // --- vectorized stores: 2x STG.128 per o-channel ---
    const int hh = h0 + pgy;
    float* obase = out + ((size_t)b * 64 + (wid << 3)) * (512 * 512)
                       + (size_t)hh * 512 + w0 + cbase;
    #pragma unroll
    for (int o = 0; o < 8; o++) {
        float4 lo = make_float4(acc[o][0], acc[o][1], acc[o][2], acc[o][3]);
        float4 hi = make_float4(acc[o][4], acc[o][5], acc[o][6], acc[o][7]);
        float4* p = reinterpret_cast<float4*>(obase + (size_t)o * 512 * 512);
        p[0] = lo;
        p[1] = hi;
    }
}

// ---------------------------------------------------------------------------
// Harness entry point.
//   d_in[0] = input  (4, 64, 512, 512) float
//   d_in[1] = style  (4, 64)           float
//   d_in[2] = weight (64, 64, 3, 3)    float
//   d_out   = (4, 64, 512, 512) float
// ---------------------------------------------------------------------------
extern "C" void kernel_launch(void* const* d_in, const int* in_sizes, int n_in,
                              void* d_out, int out_size) {
    const float* input  = (const float*)d_in[0];
    const float* style  = (const float*)d_in[1];
    const float* weight = (const float*)d_in[2];
    float* out = (float*)d_out;

    modulate_kernel<<<256, 256>>>(weight, style);

    dim3 grid(512 / 16, 512 / 16, 4);   // (32, 32, 4)
    conv_kernel<<<grid, 256>>>(input, out);
}

// round 2
// speedup vs baseline: 1.0030x; 1.0030x over previous
#include <cuda_runtime.h>
#include <cuda_bf16.h>

// Problem constants (fixed by the dataset): B=4, I=64, O=64, K=3, H=W=512.
#define EPS_F 1e-8f

// Scratch for modulated+demodulated weights, layout [b][i][o][k] (k = ky*3+kx)
// so the conv kernel can stream 576 contiguous floats per (b, i).
// 4*64*64*9 floats = 2.36 MB -> stays L2-resident across the conv kernel.
__device__ float g_wmod[4 * 64 * 64 * 9];

// ---------------------------------------------------------------------------
// Kernel 1: per-(b,o) style modulation + demodulation.
// w[b,o,i,k] = weight[o,i,k] * style[b,i];  sigma = sqrt(EPS + sum w^2)
// g_wmod[b,i,o,k] = w / sigma
// One block per (b,o): 256 blocks x 256 threads. Negligible cost (~5 us).
// ---------------------------------------------------------------------------
__global__ void modulate_kernel(const float* __restrict__ weight,   // (O, I, 3, 3)
                                const float* __restrict__ style) {  // (B, I)
    const int bo  = blockIdx.x;
    const int b   = bo >> 6;
    const int o   = bo & 63;
    const int tid = threadIdx.x;

    __shared__ float red[8];
    __shared__ float s_inv;

    float sum = 0.f;
    for (int idx = tid; idx < 576; idx += 256) {
        const int i = idx / 9;
        const float v = weight[o * 576 + idx] * style[b * 64 + i];
        sum += v * v;
    }
    #pragma unroll
    for (int off = 16; off; off >>= 1)
        sum += __shfl_down_sync(0xffffffffu, sum, off);
    if ((tid & 31) == 0) red[tid >> 5] = sum;
    __syncthreads();
    if (tid == 0) {
        float t = 0.f;
        #pragma unroll
        for (int k = 0; k < 8; k++) t += red[k];
        s_inv = rsqrtf(EPS_F + t);
    }
    __syncthreads();
    const float inv = s_inv;

    for (int idx = tid; idx < 576; idx += 256) {
        const int i = idx / 9;
        const int k = idx - i * 9;
        const float v = weight[o * 576 + idx] * style[b * 64 + i] * inv;
        g_wmod[((b * 64 + i) * 64 + o) * 9 + k] = v;
    }
}

// ---------------------------------------------------------------------------
// Kernel 2: direct 3x3 conv, one block per (b, 16x16 output tile), all 64
// output channels computed in-block (input tile read once per block).
//
// Thread layout (256 threads = 8 warps):
//   warp  (tid>>5)   -> o-group: output channels [wid*8, wid*8+8)
//                       => weight smem reads are warp-uniform broadcasts
//   lane  (tid&31)   -> pgy = lane>>1 (pixel row 0..15),
//                       cbase = (lane&1)*8 (pixel cols cbase..cbase+7)
//
// Per input channel i: 576 FFMA vs ~102 LDS per thread -> FMA-pipe bound.
// ---------------------------------------------------------------------------
__global__ __launch_bounds__(256, 2)
void conv_kernel(const float* __restrict__ input,   // (B, I, 512, 512)
                 float* __restrict__ out) {         // (B, O, 512, 512)
    __shared__ float s_in[18 * 18];   // input tile + 1-px halo (stride 18: <=2-way conflicts)
    __shared__ float s_w[64 * 9];     // all 64 output-channel filters for channel i

    const int tid   = threadIdx.x;
    const int b     = blockIdx.z;
    const int h0    = blockIdx.y << 4;
    const int w0    = blockIdx.x << 4;
    const int wid   = tid >> 5;          // o-group
    const int lane  = tid & 31;
    const int pgy   = lane >> 1;         // pixel row in tile
    const int cbase = (lane & 1) << 3;   // pixel col base in tile

    float acc[8][8];
    #pragma unroll
    for (int o = 0; o < 8; o++)
        #pragma unroll
        for (int x = 0; x < 8; x++) acc[o][x] = 0.f;

    const float* in_b = input + (size_t)b * 64 * 512 * 512;
    const float* wm_b = g_wmod + (size_t)b * 64 * 64 * 9;

    for (int i = 0; i < 64; i++) {
        __syncthreads();  // protect smem from previous iteration's readers

        // --- load 18x18 input tile (zero-padded at image border) ---
        const float* in_c = in_b + (size_t)i * 512 * 512;
        for (int idx = tid; idx < 324; idx += 256) {
            const int r  = idx / 18;
            const int c  = idx - r * 18;
            const int gh = h0 + r - 1;
            const int gw = w0 + c - 1;
            float v = 0.f;
            if ((unsigned)gh < 512u && (unsigned)gw < 512u)
                v = in_c[gh * 512 + gw];
            s_in[idx] = v;
        }
        // --- load 64x9 modulated weights for channel i ---
        const float* wsrc = wm_b + (size_t)i * 64 * 9;
        for (int idx = tid; idx < 576; idx += 256)
            s_w[idx] = wsrc[idx];

        __syncthreads();

        // --- hoist 3x10 input neighborhood to registers ---
        float v[3][10];
        #pragma unroll
        for (int dy = 0; dy < 3; dy++)
            #pragma unroll
            for (int c = 0; c < 10; c++)
                v[dy][c] = s_in[(pgy + dy) * 18 + cbase + c];

        // --- 8 o-channels x 8 pixels x 9 taps = 576 FFMA ---
        #pragma unroll
        for (int o = 0; o < 8; o++) {
            float wr[9];
            const float* wp = s_w + ((wid << 3) + o) * 9;   // warp-uniform -> LDS broadcast
            #pragma unroll
            for (int k = 0; k < 9; k++) wr[k] = wp[k];
            #pragma unroll
            for (int x = 0; x < 8; x++) {
                float a = acc[o][x];
                #pragma unroll
                for (int dy = 0; dy < 3; dy++)
                    #pragma unroll
                    for (int dx = 0; dx < 3; dx++)
                        a += wr[dy * 3 + dx] * v[dy][x + dx];
                acc[o][x] = a;
            }
        }
    }

    // --- vectorized stores: 2x STG.128 per o-channel ---
    const int hh = h0 + pgy;
    float* obase = out + ((size_t)b * 64 + (wid << 3)) * (512 * 512)
                       + (size_t)hh * 512 + w0 + cbase;
    #pragma unroll
    for (int o = 0; o < 8; o++) {
        float4 lo = make_float4(acc[o][0], acc[o][1], acc[o][2], acc[o][3]);
        float4 hi = make_float4(acc[o][4], acc[o][5], acc[o][6], acc[o][7]);
        float4* p = reinterpret_cast<float4*>(obase + (size_t)o * 512 * 512);
        p[0] = lo;
        p[1] = hi;
    }
}

// ---------------------------------------------------------------------------
// Harness entry point.
//   d_in[0] = input  (4, 64, 512, 512) float
//   d_in[1] = style  (4, 64)           float
//   d_in[2] = weight (64, 64, 3, 3)    float
//   d_out   = (4, 64, 512, 512) float
// ---------------------------------------------------------------------------
extern "C" void kernel_launch(void* const* d_in, const int* in_sizes, int n_in,
                              void* d_out, int out_size) {
    const float* input  = (const float*)d_in[0];
    const float* style  = (const float*)d_in[1];
    const float* weight = (const float*)d_in[2];
    float* out = (float*)d_out;

    modulate_kernel<<<256, 256>>>(weight, style);

    dim3 grid(512 / 16, 512 / 16, 4);   // (32, 32, 4)
    conv_kernel<<<grid, 256>>>(input, out);
}